// round 8
// baseline (speedup 1.0000x reference)
#include <cuda_runtime.h>
#include <cuda_bf16.h>
#include <math.h>

// Problem constants (fixed shapes)
#define HSZ   2048
#define NH    16
#define NKV   4
#define HD    128
#define BATCH 2
#define SEQ   2048
#define NTOK  (BATCH*SEQ)          // 4096

typedef unsigned int u32;
typedef __nv_bfloat16 bf16;

// Scratch (device globals; allocation is forbidden)
__device__ float g_qkv[(size_t)NTOK*3072];     // fused QKV output, 50.3 MB
// bf16 hi/lo split weights (transposed [N][K]); QKV packed rows 0..3071, Wo after
#define WT_TOTAL 10485760
#define WT_OFF_QKV 0
#define WT_OFF_O   6291456
__device__ bf16 g_wtbh[(size_t)WT_TOTAL];
__device__ bf16 g_wtbl[(size_t)WT_TOTAL];
// bf16 hi/lo activations
__device__ bf16 g_hsh[(size_t)NTOK*HSZ],  g_hsl[(size_t)NTOK*HSZ];
__device__ bf16 g_attnh[(size_t)NTOK*NH*HD], g_attnl[(size_t)NTOK*NH*HD];
// bf16 hi/lo attention operands
__device__ bf16 g_qh[(size_t)NTOK*NH*HD],  g_ql[(size_t)NTOK*NH*HD];
__device__ bf16 g_kh[(size_t)NTOK*NKV*HD], g_kl[(size_t)NTOK*NKV*HD];
__device__ bf16 g_vth[(size_t)BATCH*NKV*HD*SEQ], g_vtl[(size_t)BATCH*NKV*HD*SEQ];

// ---------------------------------------------------------------------------
// Helpers
// ---------------------------------------------------------------------------
__device__ __forceinline__ void mma_bf16(float* d, const u32* a, u32 b0, u32 b1) {
    asm volatile(
        "mma.sync.aligned.m16n8k16.row.col.f32.bf16.bf16.f32 "
        "{%0,%1,%2,%3}, {%4,%5,%6,%7}, {%8,%9}, {%0,%1,%2,%3};"
        : "+f"(d[0]), "+f"(d[1]), "+f"(d[2]), "+f"(d[3])
        : "r"(a[0]), "r"(a[1]), "r"(a[2]), "r"(a[3]), "r"(b0), "r"(b1));
}

__device__ __forceinline__ u32 pack_bf16(float a, float b) {
    u32 lo = (u32)__bfloat16_as_ushort(__float2bfloat16_rn(a));
    u32 hi = (u32)__bfloat16_as_ushort(__float2bfloat16_rn(b));
    return lo | (hi << 16);
}

__device__ __forceinline__ void cp_async16(u32 dst, const void* src) {
    asm volatile("cp.async.cg.shared.global [%0], [%1], 16;"
                 :: "r"(dst), "l"(src));
}
__device__ __forceinline__ void cp_commit() {
    asm volatile("cp.async.commit_group;");
}
template <int N>
__device__ __forceinline__ void cp_wait() {
    asm volatile("cp.async.wait_group %0;" :: "n"(N));
}

__device__ __forceinline__ u32 smem_u32(const void* p) {
    u32 a;
    asm("{ .reg .u64 t; cvta.to.shared.u64 t, %1; cvt.u32.u64 %0, t; }"
        : "=r"(a) : "l"(p));
    return a;
}

// ---------------------------------------------------------------------------
// Weight transpose + bf16 hi/lo split: W[K][N] -> Th[N][K], Tl[N][K] (bf16)
// ---------------------------------------------------------------------------
__global__ void transpose_split_kernel(const float* __restrict__ W,
                                       bf16* __restrict__ Th,
                                       bf16* __restrict__ Tl,
                                       int K, int N)
{
    __shared__ float t[32][33];
    const int bx = blockIdx.x * 32;
    const int by = blockIdx.y * 32;
    const int tx = threadIdx.x, ty = threadIdx.y;
#pragma unroll
    for (int j = 0; j < 4; j++)
        t[ty + j * 8][tx] = W[(size_t)(by + ty + j * 8) * N + bx + tx];
    __syncthreads();
#pragma unroll
    for (int j = 0; j < 4; j++) {
        float v = t[tx][ty + j * 8];
        bf16 h = __float2bfloat16_rn(v);
        size_t o = (size_t)(bx + ty + j * 8) * K + by + tx;
        Th[o] = h;
        Tl[o] = __float2bfloat16_rn(v - __bfloat162float(h));
    }
}

// ---------------------------------------------------------------------------
// Activation bf16 hi/lo split (elementwise, vectorized x4)
// ---------------------------------------------------------------------------
__global__ void split_act_kernel(const float* __restrict__ x,
                                 bf16* __restrict__ xh, bf16* __restrict__ xl,
                                 int total4)
{
    int i = blockIdx.x * blockDim.x + threadIdx.x;
    if (i >= total4) return;
    float4 v = *(const float4*)&x[(size_t)i * 4];
    float hx = __bfloat162float(__float2bfloat16_rn(v.x));
    float hy = __bfloat162float(__float2bfloat16_rn(v.y));
    float hz = __bfloat162float(__float2bfloat16_rn(v.z));
    float hw = __bfloat162float(__float2bfloat16_rn(v.w));
    u32* ph = (u32*)&xh[(size_t)i * 4];
    u32* pl = (u32*)&xl[(size_t)i * 4];
    ph[0] = pack_bf16(hx, hy);
    ph[1] = pack_bf16(hz, hw);
    pl[0] = pack_bf16(v.x - hx, v.y - hy);
    pl[1] = pack_bf16(v.z - hz, v.w - hw);
}

// ---------------------------------------------------------------------------
// bf16 GEMM (3xBF16, cp.async 3-stage):
//   C[M,N] = (Ah+Al)[M,2048] @ (Bh+Bl)[N,2048]^T
// CTA tile 256x128, BK=32, 512 threads (16 warps: 8 along M x 2 along N).
// smem rows padded to 40 bf16 (80B) -> conflict-free b32 fragment loads.
// ---------------------------------------------------------------------------
#define GK 2048
#define NCH 64
#define ROWB 80
#define OFF_AH 0
#define OFF_AL 20480
#define OFF_BH 40960
#define OFF_BL 51200
#define STGB 61440
#define GEMM_SMEM (3*STGB)     // 184320

__global__ void __launch_bounds__(512) gemm_bf16_kernel(
    const bf16* __restrict__ Ah, const bf16* __restrict__ Al,
    const bf16* __restrict__ Bh, const bf16* __restrict__ Bl,
    float* __restrict__ C, int N)
{
    extern __shared__ char sm[];
    const u32 smb   = smem_u32(sm);
    const int tid   = threadIdx.x;
    const int lane  = tid & 31;
    const int wid   = tid >> 5;
    const int wm    = wid >> 1;            // 0..7
    const int wn    = wid & 1;             // 0..1
    const int g     = lane >> 2;
    const int t4    = lane & 3;
    const int m0    = blockIdx.y * 256;
    const int n0    = blockIdx.x * 128;

    // Per-thread load slots (6 x 16B per stage; 3072 chunks total)
    const bf16* lsrc[6];
    u32 ldst[6];
#pragma unroll
    for (int i = 0; i < 6; i++) {
        int e = i * 512 + tid;             // 0..3071
        const bf16* base; int r, ch, off, row0;
        if (e < 1024)      { base = Ah; r = e >> 2;          ch = e & 3; off = OFF_AH; row0 = m0; }
        else if (e < 2048) { base = Al; r = (e-1024) >> 2;   ch = e & 3; off = OFF_AL; row0 = m0; }
        else if (e < 2560) { base = Bh; r = (e-2048) >> 2;   ch = e & 3; off = OFF_BH; row0 = n0; }
        else               { base = Bl; r = (e-2560) >> 2;   ch = e & 3; off = OFF_BL; row0 = n0; }
        lsrc[i] = base + (size_t)(row0 + r) * GK + ch * 8;
        ldst[i] = smb + off + r * ROWB + ch * 16;
    }

    float acc[2][8][4];
#pragma unroll
    for (int mt = 0; mt < 2; mt++)
#pragma unroll
        for (int nt = 0; nt < 8; nt++)
#pragma unroll
            for (int r = 0; r < 4; r++) acc[mt][nt][r] = 0.0f;

    // Prologue: stages 0 and 1
#pragma unroll
    for (int s = 0; s < 2; s++) {
#pragma unroll
        for (int i = 0; i < 6; i++)
            cp_async16(ldst[i] + s * STGB, lsrc[i] + s * 32);
        cp_commit();
    }

    for (int c = 0; c < NCH; c++) {
        if (c + 2 < NCH) {
            const u32 sb = ((c + 2) % 3) * STGB;
            const int koff = (c + 2) * 32;
#pragma unroll
            for (int i = 0; i < 6; i++)
                cp_async16(ldst[i] + sb, lsrc[i] + koff);
            cp_commit();
            cp_wait<2>();
        } else if (c + 1 < NCH) {
            cp_wait<1>();
        } else {
            cp_wait<0>();
        }
        __syncthreads();

        const char* st = sm + (c % 3) * STGB;
        const bf16* sAh = (const bf16*)(st + OFF_AH);
        const bf16* sAl = (const bf16*)(st + OFF_AL);
        const bf16* sBh = (const bf16*)(st + OFF_BH);
        const bf16* sBl = (const bf16*)(st + OFF_BL);

#pragma unroll
        for (int step = 0; step < 2; step++) {
            const int kb = step * 16;
            u32 ah[2][4], al[2][4];
#pragma unroll
            for (int mt = 0; mt < 2; mt++) {
                int r = wm * 32 + mt * 16 + g;
                ah[mt][0] = *(const u32*)&sAh[r * 40 + kb + t4 * 2];
                ah[mt][1] = *(const u32*)&sAh[(r + 8) * 40 + kb + t4 * 2];
                ah[mt][2] = *(const u32*)&sAh[r * 40 + kb + 8 + t4 * 2];
                ah[mt][3] = *(const u32*)&sAh[(r + 8) * 40 + kb + 8 + t4 * 2];
                al[mt][0] = *(const u32*)&sAl[r * 40 + kb + t4 * 2];
                al[mt][1] = *(const u32*)&sAl[(r + 8) * 40 + kb + t4 * 2];
                al[mt][2] = *(const u32*)&sAl[r * 40 + kb + 8 + t4 * 2];
                al[mt][3] = *(const u32*)&sAl[(r + 8) * 40 + kb + 8 + t4 * 2];
            }
#pragma unroll
            for (int nt = 0; nt < 8; nt++) {
                int n = wn * 64 + nt * 8 + g;
                u32 bh0 = *(const u32*)&sBh[n * 40 + kb + t4 * 2];
                u32 bh1 = *(const u32*)&sBh[n * 40 + kb + 8 + t4 * 2];
                u32 bl0 = *(const u32*)&sBl[n * 40 + kb + t4 * 2];
                u32 bl1 = *(const u32*)&sBl[n * 40 + kb + 8 + t4 * 2];
#pragma unroll
                for (int mt = 0; mt < 2; mt++) {
                    mma_bf16(acc[mt][nt], ah[mt], bh0, bh1);
                    mma_bf16(acc[mt][nt], ah[mt], bl0, bl1);
                    mma_bf16(acc[mt][nt], al[mt], bh0, bh1);
                }
            }
        }
        __syncthreads();
    }

    // Epilogue
#pragma unroll
    for (int mt = 0; mt < 2; mt++) {
#pragma unroll
        for (int nt = 0; nt < 8; nt++) {
            int r  = m0 + wm * 32 + mt * 16 + g;
            int cb = n0 + wn * 64 + nt * 8 + t4 * 2;
            float2 lo = {acc[mt][nt][0], acc[mt][nt][1]};
            float2 hi = {acc[mt][nt][2], acc[mt][nt][3]};
            *(float2*)&C[(size_t)r * N + cb]       = lo;
            *(float2*)&C[(size_t)(r + 8) * N + cb] = hi;
        }
    }
}

// ---------------------------------------------------------------------------
// RoPE + bf16 hi/lo split. Reads fp32 x [tok][*xstride*] (+head*HD),
// writes packed xh/xl bf16 [tok][nheads*HD].
// ---------------------------------------------------------------------------
__global__ void rope_split_kernel(const float* __restrict__ x, int xstride,
                                  bf16* __restrict__ xh, bf16* __restrict__ xl,
                                  const int* __restrict__ pos_ids,
                                  int nheads, int total, float outscale)
{
    int idx = blockIdx.x * blockDim.x + threadIdx.x;
    if (idx >= total) return;
    int j = idx & 63;
    int t = idx >> 6;
    int tok = t / nheads;
    int head = t - tok * nheads;

    int pos = pos_ids[tok];

    float invf = (float)exp(-(double)j * (9.210340371976184 / 64.0));
    float angf = (float)pos * invf;
    double r = remainder((double)angf, 6.283185307179586);
    float c, s;
    sincosf((float)r, &s, &c);

    const float* base = x + (size_t)tok * xstride + head * HD;
    float x1 = base[j];
    float x2 = base[j + 64];
    float o1 = (x1 * c - x2 * s) * outscale;
    float o2 = (x2 * c + x1 * s) * outscale;

    size_t o = (size_t)t * HD;
    bf16 h1 = __float2bfloat16_rn(o1);
    bf16 h2 = __float2bfloat16_rn(o2);
    xh[o + j]      = h1;
    xh[o + j + 64] = h2;
    xl[o + j]      = __float2bfloat16_rn(o1 - __bfloat162float(h1));
    xl[o + j + 64] = __float2bfloat16_rn(o2 - __bfloat162float(h2));
}

// ---------------------------------------------------------------------------
// V transpose + bf16 split: V from strided buffer -> Vt[(b,hk),d,s] hi/lo
// ---------------------------------------------------------------------------
__global__ void vt_split_kernel(const float* __restrict__ V, int vstride,
                                bf16* __restrict__ Vth, bf16* __restrict__ Vtl)
{
    __shared__ float t[32][33];
    const int b  = blockIdx.z >> 2;
    const int hk = blockIdx.z & 3;
    const int s0 = blockIdx.x * 32;
    const int d0 = blockIdx.y * 32;
    const int tx = threadIdx.x, ty = threadIdx.y;
#pragma unroll
    for (int j = 0; j < 4; j++)
        t[ty + j * 8][tx] =
            V[(size_t)(b * SEQ + s0 + ty + j * 8) * vstride + hk * HD + d0 + tx];
    __syncthreads();
#pragma unroll
    for (int j = 0; j < 4; j++) {
        float v = t[tx][ty + j * 8];
        bf16 h = __float2bfloat16_rn(v);
        size_t o = ((size_t)(b * NKV + hk) * HD + d0 + ty + j * 8) * SEQ + s0 + tx;
        Vth[o] = h;
        Vtl[o] = __float2bfloat16_rn(v - __bfloat162float(h));
    }
}

// ---------------------------------------------------------------------------
// Flash attention, mma.sync bf16 (3xBF16), cp.async double-buffered K/V.
// CTA: 128 queries x one (b,h). 256 threads. Writes bf16 hi/lo.
// ---------------------------------------------------------------------------
#define KSTR 136
#define VSTR 72
#define SK_H 0
#define SK_L (64*KSTR)
#define SV_H (2*64*KSTR)
#define SV_L (2*64*KSTR + 128*VSTR)
#define STG_ELTS (2*64*KSTR + 2*128*VSTR)          // 35840 bf16
#define FLASH_SMEM (2*STG_ELTS*2)                  // 143360 bytes

__global__ void __launch_bounds__(256, 1) flash_mma_kernel(
    const bf16* __restrict__ Qh, const bf16* __restrict__ Ql,
    const bf16* __restrict__ Kh, const bf16* __restrict__ Kl,
    const bf16* __restrict__ Vth, const bf16* __restrict__ Vtl,
    bf16* __restrict__ Oh, bf16* __restrict__ Ol)
{
    extern __shared__ bf16 smf[];
    const u32 smb = smem_u32(smf);
    const int qt  = blockIdx.x;
    const int h   = blockIdx.y;
    const int b   = blockIdx.z;
    const int hk  = h >> 2;
    const int tid = threadIdx.x;
    const int wid = tid >> 5;
    const int lane = tid & 31;
    const int g   = lane >> 2;
    const int t4  = lane & 3;
    const int q0  = qt * 128;

    const int r0 = q0 + wid * 16 + g;
    const int r1 = r0 + 8;

    // Per-thread cp.async slots (16 per stage)
    const bf16* lsrc[16];   // base (kt=0); K slots advance 64*512, V slots 64
    u32 lofs[16];           // smem offset within stage (bytes)
    int lstep[16];
    {
        const size_t kb = ((size_t)(b * SEQ) * NKV + hk) * HD;
        const size_t vb = ((size_t)(b * NKV + hk) * HD) * SEQ;
#pragma unroll
        for (int i = 0; i < 16; i++) {
            int e = i * 256 + tid;
            if (e < 2048) {
                int hl = e >> 10, r = (e >> 4) & 63, c4 = e & 15;
                lsrc[i]  = (hl ? Kl : Kh) + kb + (size_t)r * (NKV * HD) + c4 * 8;
                lofs[i]  = ((hl ? SK_L : SK_H) + r * KSTR + c4 * 8) * 2;
                lstep[i] = 64 * NKV * HD;
            } else {
                int e2 = e - 2048;
                int hl = e2 >> 10, d = (e2 >> 3) & 127, c4 = e2 & 7;
                lsrc[i]  = (hl ? Vtl : Vth) + vb + (size_t)d * SEQ + c4 * 8;
                lofs[i]  = ((hl ? SV_L : SV_H) + d * VSTR + c4 * 8) * 2;
                lstep[i] = 64;
            }
        }
    }

    // Q fragments in registers
    u32 qfh[8][4], qfl[8][4];
    {
        const size_t b0 = ((size_t)(b * SEQ + r0) * NH + h) * HD;
        const size_t b1 = ((size_t)(b * SEQ + r1) * NH + h) * HD;
#pragma unroll
        for (int s = 0; s < 8; s++) {
            int d0 = s * 16 + t4 * 2, d1 = d0 + 8;
            qfh[s][0] = *(const u32*)&Qh[b0 + d0];
            qfh[s][1] = *(const u32*)&Qh[b1 + d0];
            qfh[s][2] = *(const u32*)&Qh[b0 + d1];
            qfh[s][3] = *(const u32*)&Qh[b1 + d1];
            qfl[s][0] = *(const u32*)&Ql[b0 + d0];
            qfl[s][1] = *(const u32*)&Ql[b1 + d0];
            qfl[s][2] = *(const u32*)&Ql[b0 + d1];
            qfl[s][3] = *(const u32*)&Ql[b1 + d1];
        }
    }

    float oacc[16][4];
#pragma unroll
    for (int nt = 0; nt < 16; nt++)
#pragma unroll
        for (int r = 0; r < 4; r++) oacc[nt][r] = 0.0f;
    float m0 = -1e30f, m1 = -1e30f, l0 = 0.0f, l1 = 0.0f;

    const int nkt = 2 * qt + 2;

    // Prologue: kt=0 into stage 0
#pragma unroll
    for (int i = 0; i < 16; i++)
        cp_async16(smb + lofs[i], lsrc[i]);
    cp_commit();

    for (int kt = 0; kt < nkt; kt++) {
        const int k0 = kt * 64;
        if (kt + 1 < nkt) {
            const u32 sb = ((kt + 1) & 1) * (STG_ELTS * 2);
#pragma unroll
            for (int i = 0; i < 16; i++)
                cp_async16(smb + sb + lofs[i], lsrc[i] + (size_t)(kt + 1) * lstep[i]);
            cp_commit();
            cp_wait<1>();
        } else {
            cp_wait<0>();
        }
        __syncthreads();

        const bf16* st = smf + (kt & 1) * STG_ELTS;

        const bool active = (k0 <= q0 + wid * 16 + 15);
        if (active) {
            float sacc[8][4];
#pragma unroll
            for (int j = 0; j < 8; j++)
#pragma unroll
                for (int r = 0; r < 4; r++) sacc[j][r] = 0.0f;

#pragma unroll
            for (int s = 0; s < 8; s++) {
#pragma unroll
                for (int j = 0; j < 8; j++) {
                    int key = j * 8 + g;
                    u32 bh0 = *(const u32*)&st[SK_H + key * KSTR + s * 16 + t4 * 2];
                    u32 bh1 = *(const u32*)&st[SK_H + key * KSTR + s * 16 + 8 + t4 * 2];
                    u32 bl0 = *(const u32*)&st[SK_L + key * KSTR + s * 16 + t4 * 2];
                    u32 bl1 = *(const u32*)&st[SK_L + key * KSTR + s * 16 + 8 + t4 * 2];
                    mma_bf16(sacc[j], qfh[s], bh0, bh1);
                    mma_bf16(sacc[j], qfh[s], bl0, bl1);
                    mma_bf16(sacc[j], qfl[s], bh0, bh1);
                }
            }

            if (k0 + 63 > q0) {
#pragma unroll
                for (int j = 0; j < 8; j++) {
                    int c0 = k0 + j * 8 + t4 * 2;
                    if (c0     > r0) sacc[j][0] = -1e30f;
                    if (c0 + 1 > r0) sacc[j][1] = -1e30f;
                    if (c0     > r1) sacc[j][2] = -1e30f;
                    if (c0 + 1 > r1) sacc[j][3] = -1e30f;
                }
            }

            float rm0 = -1e30f, rm1 = -1e30f;
#pragma unroll
            for (int j = 0; j < 8; j++) {
                rm0 = fmaxf(rm0, fmaxf(sacc[j][0], sacc[j][1]));
                rm1 = fmaxf(rm1, fmaxf(sacc[j][2], sacc[j][3]));
            }
            rm0 = fmaxf(rm0, __shfl_xor_sync(0xffffffffu, rm0, 1));
            rm0 = fmaxf(rm0, __shfl_xor_sync(0xffffffffu, rm0, 2));
            rm1 = fmaxf(rm1, __shfl_xor_sync(0xffffffffu, rm1, 1));
            rm1 = fmaxf(rm1, __shfl_xor_sync(0xffffffffu, rm1, 2));
            float mn0 = fmaxf(m0, rm0), mn1 = fmaxf(m1, rm1);
            float a0 = __expf(m0 - mn0), a1 = __expf(m1 - mn1);
            m0 = mn0; m1 = mn1;
            float rs0 = 0.0f, rs1 = 0.0f;
#pragma unroll
            for (int j = 0; j < 8; j++) {
                sacc[j][0] = __expf(sacc[j][0] - m0);
                sacc[j][1] = __expf(sacc[j][1] - m0);
                sacc[j][2] = __expf(sacc[j][2] - m1);
                sacc[j][3] = __expf(sacc[j][3] - m1);
                rs0 += sacc[j][0] + sacc[j][1];
                rs1 += sacc[j][2] + sacc[j][3];
            }
            rs0 += __shfl_xor_sync(0xffffffffu, rs0, 1);
            rs0 += __shfl_xor_sync(0xffffffffu, rs0, 2);
            rs1 += __shfl_xor_sync(0xffffffffu, rs1, 1);
            rs1 += __shfl_xor_sync(0xffffffffu, rs1, 2);
            l0 = l0 * a0 + rs0;
            l1 = l1 * a1 + rs1;
#pragma unroll
            for (int nt = 0; nt < 16; nt++) {
                oacc[nt][0] *= a0; oacc[nt][1] *= a0;
                oacc[nt][2] *= a1; oacc[nt][3] *= a1;
            }

            u32 pfh[4][4], pfl[4][4];
#pragma unroll
            for (int s = 0; s < 4; s++) {
                int j0 = 2 * s, j1 = 2 * s + 1;
                float h00, h01, h10, h11, h20, h21, h30, h31;
                h00 = __bfloat162float(__float2bfloat16_rn(sacc[j0][0]));
                h01 = __bfloat162float(__float2bfloat16_rn(sacc[j0][1]));
                h10 = __bfloat162float(__float2bfloat16_rn(sacc[j0][2]));
                h11 = __bfloat162float(__float2bfloat16_rn(sacc[j0][3]));
                h20 = __bfloat162float(__float2bfloat16_rn(sacc[j1][0]));
                h21 = __bfloat162float(__float2bfloat16_rn(sacc[j1][1]));
                h30 = __bfloat162float(__float2bfloat16_rn(sacc[j1][2]));
                h31 = __bfloat162float(__float2bfloat16_rn(sacc[j1][3]));
                pfh[s][0] = pack_bf16(h00, h01);
                pfh[s][1] = pack_bf16(h10, h11);
                pfh[s][2] = pack_bf16(h20, h21);
                pfh[s][3] = pack_bf16(h30, h31);
                pfl[s][0] = pack_bf16(sacc[j0][0] - h00, sacc[j0][1] - h01);
                pfl[s][1] = pack_bf16(sacc[j0][2] - h10, sacc[j0][3] - h11);
                pfl[s][2] = pack_bf16(sacc[j1][0] - h20, sacc[j1][1] - h21);
                pfl[s][3] = pack_bf16(sacc[j1][2] - h30, sacc[j1][3] - h31);
            }

#pragma unroll
            for (int s = 0; s < 4; s++) {
#pragma unroll
                for (int nt = 0; nt < 16; nt++) {
                    int d = nt * 8 + g;
                    u32 vh0 = *(const u32*)&st[SV_H + d * VSTR + s * 16 + t4 * 2];
                    u32 vh1 = *(const u32*)&st[SV_H + d * VSTR + s * 16 + 8 + t4 * 2];
                    u32 vl0 = *(const u32*)&st[SV_L + d * VSTR + s * 16 + t4 * 2];
                    u32 vl1 = *(const u32*)&st[SV_L + d * VSTR + s * 16 + 8 + t4 * 2];
                    mma_bf16(oacc[nt], pfh[s], vh0, vh1);
                    mma_bf16(oacc[nt], pfh[s], vl0, vl1);
                    mma_bf16(oacc[nt], pfl[s], vh0, vh1);
                }
            }
        }
        __syncthreads();
    }

    // Epilogue: write bf16 hi/lo (feeds Wo GEMM)
    float il0 = 1.0f / l0, il1 = 1.0f / l1;
    const size_t ob0 = ((size_t)(b * SEQ + r0) * NH + h) * HD;
    const size_t ob1 = ((size_t)(b * SEQ + r1) * NH + h) * HD;
#pragma unroll
    for (int nt = 0; nt < 16; nt++) {
        int cb = nt * 8 + t4 * 2;
        float o00 = oacc[nt][0] * il0, o01 = oacc[nt][1] * il0;
        float o10 = oacc[nt][2] * il1, o11 = oacc[nt][3] * il1;
        float h00 = __bfloat162float(__float2bfloat16_rn(o00));
        float h01 = __bfloat162float(__float2bfloat16_rn(o01));
        float h10 = __bfloat162float(__float2bfloat16_rn(o10));
        float h11 = __bfloat162float(__float2bfloat16_rn(o11));
        *(u32*)&Oh[ob0 + cb] = pack_bf16(h00, h01);
        *(u32*)&Oh[ob1 + cb] = pack_bf16(h10, h11);
        *(u32*)&Ol[ob0 + cb] = pack_bf16(o00 - h00, o01 - h01);
        *(u32*)&Ol[ob1 + cb] = pack_bf16(o10 - h10, o11 - h11);
    }
}

// ---------------------------------------------------------------------------
// Launch
// ---------------------------------------------------------------------------
extern "C" void kernel_launch(void* const* d_in, const int* in_sizes, int n_in,
                              void* d_out, int out_size)
{
    const float* hs  = (const float*)d_in[0];
    const int*   pos = (const int*)d_in[1];
    const float* Wq  = (const float*)d_in[2];
    const float* Wk  = (const float*)d_in[3];
    const float* Wv  = (const float*)d_in[4];
    const float* Wo  = (const float*)d_in[5];
    float*       out = (float*)d_out;

    float *qkv;
    bf16 *wtbh, *wtbl, *hsh, *hsl, *attnh, *attnl;
    bf16 *qh, *ql, *kh, *kl, *vth, *vtl;
    cudaGetSymbolAddress((void**)&qkv,   g_qkv);
    cudaGetSymbolAddress((void**)&wtbh,  g_wtbh);
    cudaGetSymbolAddress((void**)&wtbl,  g_wtbl);
    cudaGetSymbolAddress((void**)&hsh,   g_hsh);
    cudaGetSymbolAddress((void**)&hsl,   g_hsl);
    cudaGetSymbolAddress((void**)&attnh, g_attnh);
    cudaGetSymbolAddress((void**)&attnl, g_attnl);
    cudaGetSymbolAddress((void**)&qh,    g_qh);
    cudaGetSymbolAddress((void**)&ql,    g_ql);
    cudaGetSymbolAddress((void**)&kh,    g_kh);
    cudaGetSymbolAddress((void**)&kl,    g_kl);
    cudaGetSymbolAddress((void**)&vth,   g_vth);
    cudaGetSymbolAddress((void**)&vtl,   g_vtl);

    cudaFuncSetAttribute(flash_mma_kernel,
                         cudaFuncAttributeMaxDynamicSharedMemorySize, FLASH_SMEM);
    cudaFuncSetAttribute(gemm_bf16_kernel,
                         cudaFuncAttributeMaxDynamicSharedMemorySize, GEMM_SMEM);

    // Weight transpose + bf16 split: QKV packed [3072][2048], Wo after
    transpose_split_kernel<<<dim3(2048/32, 2048/32), dim3(32, 8)>>>(
        Wq, wtbh + WT_OFF_QKV,                  wtbl + WT_OFF_QKV,                  HSZ, 2048);
    transpose_split_kernel<<<dim3(512/32, 2048/32), dim3(32, 8)>>>(
        Wk, wtbh + WT_OFF_QKV + 2048*HSZ,       wtbl + WT_OFF_QKV + 2048*HSZ,       HSZ, 512);
    transpose_split_kernel<<<dim3(512/32, 2048/32), dim3(32, 8)>>>(
        Wv, wtbh + WT_OFF_QKV + 2560*HSZ,       wtbl + WT_OFF_QKV + 2560*HSZ,       HSZ, 512);
    transpose_split_kernel<<<dim3(2048/32, 2048/32), dim3(32, 8)>>>(
        Wo, wtbh + WT_OFF_O,                    wtbl + WT_OFF_O,                    HSZ, 2048);

    // hidden_states bf16 split
    split_act_kernel<<<(NTOK * HSZ / 4 + 255) / 256, 256>>>(
        hs, hsh, hsl, NTOK * HSZ / 4);

    // Fused QKV projection (3xBF16 cp.async GEMM, N=3072)
    gemm_bf16_kernel<<<dim3(3072/128, NTOK/256), 512, GEMM_SMEM>>>(
        hsh, hsl, wtbh + WT_OFF_QKV, wtbl + WT_OFF_QKV, qkv, 3072);

    // RoPE + bf16 split; V transpose+split (all read from strided qkv)
    {
        int total_q = NTOK * NH * 64;
        int total_k = NTOK * NKV * 64;
        rope_split_kernel<<<(total_q + 255) / 256, 256>>>(
            qkv, 3072, qh, ql, pos, NH, total_q, 0.08838834764831845f);
        rope_split_kernel<<<(total_k + 255) / 256, 256>>>(
            qkv + 2048, 3072, kh, kl, pos, NKV, total_k, 1.0f);
        vt_split_kernel<<<dim3(SEQ/32, HD/32, BATCH*NKV), dim3(32, 8)>>>(
            qkv + 2560, 3072, vth, vtl);
    }

    // Causal GQA attention (3xBF16, cp.async double-buffered)
    flash_mma_kernel<<<dim3(SEQ/128, NH, BATCH), 256, FLASH_SMEM>>>(
        qh, ql, kh, kl, vth, vtl, attnh, attnl);

    // Output projection (3xBF16 cp.async GEMM)
    gemm_bf16_kernel<<<dim3(2048/128, NTOK/256), 512, GEMM_SMEM>>>(
        attnh, attnl, wtbh + WT_OFF_O, wtbl + WT_OFF_O, out, 2048);
}

// round 9
// speedup vs baseline: 1.0067x; 1.0067x over previous
#include <cuda_runtime.h>
#include <cuda_bf16.h>
#include <math.h>

// Problem constants (fixed shapes)
#define HSZ   2048
#define NH    16
#define NKV   4
#define HD    128
#define BATCH 2
#define SEQ   2048
#define NTOK  (BATCH*SEQ)          // 4096

typedef unsigned int u32;
typedef __nv_bfloat16 bf16;

// Scratch (device globals; allocation is forbidden)
__device__ float g_qkv[(size_t)NTOK*3072];     // fused QKV output, 50.3 MB
// bf16 hi/lo split weights (transposed [N][K]); QKV packed rows 0..3071, Wo after
#define WT_TOTAL 10485760
#define WT_OFF_QKV 0
#define WT_OFF_O   6291456
__device__ bf16 g_wtbh[(size_t)WT_TOTAL];
__device__ bf16 g_wtbl[(size_t)WT_TOTAL];
// bf16 hi/lo activations
__device__ bf16 g_hsh[(size_t)NTOK*HSZ],  g_hsl[(size_t)NTOK*HSZ];
__device__ bf16 g_attnh[(size_t)NTOK*NH*HD], g_attnl[(size_t)NTOK*NH*HD];
// bf16 hi/lo attention operands
__device__ bf16 g_qh[(size_t)NTOK*NH*HD],  g_ql[(size_t)NTOK*NH*HD];
__device__ bf16 g_kh[(size_t)NTOK*NKV*HD], g_kl[(size_t)NTOK*NKV*HD];
__device__ bf16 g_vth[(size_t)BATCH*NKV*HD*SEQ], g_vtl[(size_t)BATCH*NKV*HD*SEQ];

// ---------------------------------------------------------------------------
// Helpers
// ---------------------------------------------------------------------------
__device__ __forceinline__ void mma_bf16(float* d, const u32* a, u32 b0, u32 b1) {
    asm volatile(
        "mma.sync.aligned.m16n8k16.row.col.f32.bf16.bf16.f32 "
        "{%0,%1,%2,%3}, {%4,%5,%6,%7}, {%8,%9}, {%0,%1,%2,%3};"
        : "+f"(d[0]), "+f"(d[1]), "+f"(d[2]), "+f"(d[3])
        : "r"(a[0]), "r"(a[1]), "r"(a[2]), "r"(a[3]), "r"(b0), "r"(b1));
}

__device__ __forceinline__ u32 pack_bf16(float a, float b) {
    u32 lo = (u32)__bfloat16_as_ushort(__float2bfloat16_rn(a));
    u32 hi = (u32)__bfloat16_as_ushort(__float2bfloat16_rn(b));
    return lo | (hi << 16);
}

__device__ __forceinline__ void cp_async16(u32 dst, const void* src) {
    asm volatile("cp.async.cg.shared.global [%0], [%1], 16;"
                 :: "r"(dst), "l"(src));
}
__device__ __forceinline__ void cp_commit() {
    asm volatile("cp.async.commit_group;");
}
template <int N>
__device__ __forceinline__ void cp_wait() {
    asm volatile("cp.async.wait_group %0;" :: "n"(N));
}

__device__ __forceinline__ u32 smem_u32(const void* p) {
    u32 a;
    asm("{ .reg .u64 t; cvta.to.shared.u64 t, %1; cvt.u32.u64 %0, t; }"
        : "=r"(a) : "l"(p));
    return a;
}

// ---------------------------------------------------------------------------
// Weight transpose + bf16 hi/lo split: W[K][N] -> Th[N][K], Tl[N][K] (bf16)
// ---------------------------------------------------------------------------
__global__ void transpose_split_kernel(const float* __restrict__ W,
                                       bf16* __restrict__ Th,
                                       bf16* __restrict__ Tl,
                                       int K, int N)
{
    __shared__ float t[32][33];
    const int bx = blockIdx.x * 32;
    const int by = blockIdx.y * 32;
    const int tx = threadIdx.x, ty = threadIdx.y;
#pragma unroll
    for (int j = 0; j < 4; j++)
        t[ty + j * 8][tx] = W[(size_t)(by + ty + j * 8) * N + bx + tx];
    __syncthreads();
#pragma unroll
    for (int j = 0; j < 4; j++) {
        float v = t[tx][ty + j * 8];
        bf16 h = __float2bfloat16_rn(v);
        size_t o = (size_t)(bx + ty + j * 8) * K + by + tx;
        Th[o] = h;
        Tl[o] = __float2bfloat16_rn(v - __bfloat162float(h));
    }
}

// ---------------------------------------------------------------------------
// Activation bf16 hi/lo split (elementwise, vectorized x4)
// ---------------------------------------------------------------------------
__global__ void split_act_kernel(const float* __restrict__ x,
                                 bf16* __restrict__ xh, bf16* __restrict__ xl,
                                 int total4)
{
    int i = blockIdx.x * blockDim.x + threadIdx.x;
    if (i >= total4) return;
    float4 v = *(const float4*)&x[(size_t)i * 4];
    float hx = __bfloat162float(__float2bfloat16_rn(v.x));
    float hy = __bfloat162float(__float2bfloat16_rn(v.y));
    float hz = __bfloat162float(__float2bfloat16_rn(v.z));
    float hw = __bfloat162float(__float2bfloat16_rn(v.w));
    u32* ph = (u32*)&xh[(size_t)i * 4];
    u32* pl = (u32*)&xl[(size_t)i * 4];
    ph[0] = pack_bf16(hx, hy);
    ph[1] = pack_bf16(hz, hw);
    pl[0] = pack_bf16(v.x - hx, v.y - hy);
    pl[1] = pack_bf16(v.z - hz, v.w - hw);
}

// ---------------------------------------------------------------------------
// bf16 GEMM (3xBF16, cp.async 3-stage):
//   C[M,N] = (Ah+Al)[M,2048] @ (Bh+Bl)[N,2048]^T
// CTA tile 256x128, BK=32, 512 threads (16 warps: 8 along M x 2 along N).
// ---------------------------------------------------------------------------
#define GK 2048
#define NCH 64
#define ROWB 80
#define OFF_AH 0
#define OFF_AL 20480
#define OFF_BH 40960
#define OFF_BL 51200
#define STGB 61440
#define GEMM_SMEM (3*STGB)     // 184320

__global__ void __launch_bounds__(512) gemm_bf16_kernel(
    const bf16* __restrict__ Ah, const bf16* __restrict__ Al,
    const bf16* __restrict__ Bh, const bf16* __restrict__ Bl,
    float* __restrict__ C, int N)
{
    extern __shared__ char sm[];
    const u32 smb   = smem_u32(sm);
    const int tid   = threadIdx.x;
    const int lane  = tid & 31;
    const int wid   = tid >> 5;
    const int wm    = wid >> 1;
    const int wn    = wid & 1;
    const int g     = lane >> 2;
    const int t4    = lane & 3;
    const int m0    = blockIdx.y * 256;
    const int n0    = blockIdx.x * 128;

    const bf16* lsrc[6];
    u32 ldst[6];
#pragma unroll
    for (int i = 0; i < 6; i++) {
        int e = i * 512 + tid;
        const bf16* base; int r, ch, off, row0;
        if (e < 1024)      { base = Ah; r = e >> 2;          ch = e & 3; off = OFF_AH; row0 = m0; }
        else if (e < 2048) { base = Al; r = (e-1024) >> 2;   ch = e & 3; off = OFF_AL; row0 = m0; }
        else if (e < 2560) { base = Bh; r = (e-2048) >> 2;   ch = e & 3; off = OFF_BH; row0 = n0; }
        else               { base = Bl; r = (e-2560) >> 2;   ch = e & 3; off = OFF_BL; row0 = n0; }
        lsrc[i] = base + (size_t)(row0 + r) * GK + ch * 8;
        ldst[i] = smb + off + r * ROWB + ch * 16;
    }

    float acc[2][8][4];
#pragma unroll
    for (int mt = 0; mt < 2; mt++)
#pragma unroll
        for (int nt = 0; nt < 8; nt++)
#pragma unroll
            for (int r = 0; r < 4; r++) acc[mt][nt][r] = 0.0f;

#pragma unroll
    for (int s = 0; s < 2; s++) {
#pragma unroll
        for (int i = 0; i < 6; i++)
            cp_async16(ldst[i] + s * STGB, lsrc[i] + s * 32);
        cp_commit();
    }

    for (int c = 0; c < NCH; c++) {
        if (c + 2 < NCH) {
            const u32 sb = ((c + 2) % 3) * STGB;
            const int koff = (c + 2) * 32;
#pragma unroll
            for (int i = 0; i < 6; i++)
                cp_async16(ldst[i] + sb, lsrc[i] + koff);
            cp_commit();
            cp_wait<2>();
        } else if (c + 1 < NCH) {
            cp_wait<1>();
        } else {
            cp_wait<0>();
        }
        __syncthreads();

        const char* st = sm + (c % 3) * STGB;
        const bf16* sAh = (const bf16*)(st + OFF_AH);
        const bf16* sAl = (const bf16*)(st + OFF_AL);
        const bf16* sBh = (const bf16*)(st + OFF_BH);
        const bf16* sBl = (const bf16*)(st + OFF_BL);

#pragma unroll
        for (int step = 0; step < 2; step++) {
            const int kb = step * 16;
            u32 ah[2][4], al[2][4];
#pragma unroll
            for (int mt = 0; mt < 2; mt++) {
                int r = wm * 32 + mt * 16 + g;
                ah[mt][0] = *(const u32*)&sAh[r * 40 + kb + t4 * 2];
                ah[mt][1] = *(const u32*)&sAh[(r + 8) * 40 + kb + t4 * 2];
                ah[mt][2] = *(const u32*)&sAh[r * 40 + kb + 8 + t4 * 2];
                ah[mt][3] = *(const u32*)&sAh[(r + 8) * 40 + kb + 8 + t4 * 2];
                al[mt][0] = *(const u32*)&sAl[r * 40 + kb + t4 * 2];
                al[mt][1] = *(const u32*)&sAl[(r + 8) * 40 + kb + t4 * 2];
                al[mt][2] = *(const u32*)&sAl[r * 40 + kb + 8 + t4 * 2];
                al[mt][3] = *(const u32*)&sAl[(r + 8) * 40 + kb + 8 + t4 * 2];
            }
#pragma unroll
            for (int nt = 0; nt < 8; nt++) {
                int n = wn * 64 + nt * 8 + g;
                u32 bh0 = *(const u32*)&sBh[n * 40 + kb + t4 * 2];
                u32 bh1 = *(const u32*)&sBh[n * 40 + kb + 8 + t4 * 2];
                u32 bl0 = *(const u32*)&sBl[n * 40 + kb + t4 * 2];
                u32 bl1 = *(const u32*)&sBl[n * 40 + kb + 8 + t4 * 2];
#pragma unroll
                for (int mt = 0; mt < 2; mt++) {
                    mma_bf16(acc[mt][nt], ah[mt], bh0, bh1);
                    mma_bf16(acc[mt][nt], ah[mt], bl0, bl1);
                    mma_bf16(acc[mt][nt], al[mt], bh0, bh1);
                }
            }
        }
        __syncthreads();
    }

#pragma unroll
    for (int mt = 0; mt < 2; mt++) {
#pragma unroll
        for (int nt = 0; nt < 8; nt++) {
            int r  = m0 + wm * 32 + mt * 16 + g;
            int cb = n0 + wn * 64 + nt * 8 + t4 * 2;
            float2 lo = {acc[mt][nt][0], acc[mt][nt][1]};
            float2 hi = {acc[mt][nt][2], acc[mt][nt][3]};
            *(float2*)&C[(size_t)r * N + cb]       = lo;
            *(float2*)&C[(size_t)(r + 8) * N + cb] = hi;
        }
    }
}

// ---------------------------------------------------------------------------
// RoPE + bf16 hi/lo split (reads strided fp32, writes packed bf16 hi/lo)
// ---------------------------------------------------------------------------
__global__ void rope_split_kernel(const float* __restrict__ x, int xstride,
                                  bf16* __restrict__ xh, bf16* __restrict__ xl,
                                  const int* __restrict__ pos_ids,
                                  int nheads, int total, float outscale)
{
    int idx = blockIdx.x * blockDim.x + threadIdx.x;
    if (idx >= total) return;
    int j = idx & 63;
    int t = idx >> 6;
    int tok = t / nheads;
    int head = t - tok * nheads;

    int pos = pos_ids[tok];

    float invf = (float)exp(-(double)j * (9.210340371976184 / 64.0));
    float angf = (float)pos * invf;
    double r = remainder((double)angf, 6.283185307179586);
    float c, s;
    sincosf((float)r, &s, &c);

    const float* base = x + (size_t)tok * xstride + head * HD;
    float x1 = base[j];
    float x2 = base[j + 64];
    float o1 = (x1 * c - x2 * s) * outscale;
    float o2 = (x2 * c + x1 * s) * outscale;

    size_t o = (size_t)t * HD;
    bf16 h1 = __float2bfloat16_rn(o1);
    bf16 h2 = __float2bfloat16_rn(o2);
    xh[o + j]      = h1;
    xh[o + j + 64] = h2;
    xl[o + j]      = __float2bfloat16_rn(o1 - __bfloat162float(h1));
    xl[o + j + 64] = __float2bfloat16_rn(o2 - __bfloat162float(h2));
}

// ---------------------------------------------------------------------------
// V transpose + bf16 split: V from strided buffer -> Vt[(b,hk),d,s] hi/lo
// ---------------------------------------------------------------------------
__global__ void vt_split_kernel(const float* __restrict__ V, int vstride,
                                bf16* __restrict__ Vth, bf16* __restrict__ Vtl)
{
    __shared__ float t[32][33];
    const int b  = blockIdx.z >> 2;
    const int hk = blockIdx.z & 3;
    const int s0 = blockIdx.x * 32;
    const int d0 = blockIdx.y * 32;
    const int tx = threadIdx.x, ty = threadIdx.y;
#pragma unroll
    for (int j = 0; j < 4; j++)
        t[ty + j * 8][tx] =
            V[(size_t)(b * SEQ + s0 + ty + j * 8) * vstride + hk * HD + d0 + tx];
    __syncthreads();
#pragma unroll
    for (int j = 0; j < 4; j++) {
        float v = t[tx][ty + j * 8];
        bf16 h = __float2bfloat16_rn(v);
        size_t o = ((size_t)(b * NKV + hk) * HD + d0 + ty + j * 8) * SEQ + s0 + tx;
        Vth[o] = h;
        Vtl[o] = __float2bfloat16_rn(v - __bfloat162float(h));
    }
}

// ---------------------------------------------------------------------------
// Flash attention, mma.sync bf16 (3xBF16). Causal, GQA.
// CTA: 64 queries x one (b,h), 128 threads (4 warps x 16 rows).
// Single-buffered K/V tiles (64 keys); 2 CTAs/SM for cross-CTA overlap.
// qt reversed so longest CTAs launch first (causal balance).
// ---------------------------------------------------------------------------
#define KSTR 136
#define VSTR 72
#define SK_H 0
#define SK_L (64*KSTR)
#define SV_H (2*64*KSTR)
#define SV_L (2*64*KSTR + 128*VSTR)
#define FLASH_SMEM ((2*64*KSTR + 2*128*VSTR) * 2)   // 71680 bytes

__global__ void __launch_bounds__(128, 2) flash_mma_kernel(
    const bf16* __restrict__ Qh, const bf16* __restrict__ Ql,
    const bf16* __restrict__ Kh, const bf16* __restrict__ Kl,
    const bf16* __restrict__ Vth, const bf16* __restrict__ Vtl,
    bf16* __restrict__ Oh, bf16* __restrict__ Ol)
{
    extern __shared__ bf16 smf[];
    const int qt  = gridDim.x - 1 - blockIdx.x;   // longest first
    const int h   = blockIdx.y;
    const int b   = blockIdx.z;
    const int hk  = h >> 2;
    const int tid = threadIdx.x;
    const int wid = tid >> 5;          // 0..3
    const int lane = tid & 31;
    const int g   = lane >> 2;
    const int t4  = lane & 3;
    const int q0  = qt * 64;

    const int r0 = q0 + wid * 16 + g;
    const int r1 = r0 + 8;

    // Q fragments in registers (once per CTA)
    u32 qfh[8][4], qfl[8][4];
    {
        const size_t b0 = ((size_t)(b * SEQ + r0) * NH + h) * HD;
        const size_t b1 = ((size_t)(b * SEQ + r1) * NH + h) * HD;
#pragma unroll
        for (int s = 0; s < 8; s++) {
            int d0 = s * 16 + t4 * 2, d1 = d0 + 8;
            qfh[s][0] = *(const u32*)&Qh[b0 + d0];
            qfh[s][1] = *(const u32*)&Qh[b1 + d0];
            qfh[s][2] = *(const u32*)&Qh[b0 + d1];
            qfh[s][3] = *(const u32*)&Qh[b1 + d1];
            qfl[s][0] = *(const u32*)&Ql[b0 + d0];
            qfl[s][1] = *(const u32*)&Ql[b1 + d0];
            qfl[s][2] = *(const u32*)&Ql[b0 + d1];
            qfl[s][3] = *(const u32*)&Ql[b1 + d1];
        }
    }

    float oacc[16][4];
#pragma unroll
    for (int nt = 0; nt < 16; nt++)
#pragma unroll
        for (int r = 0; r < 4; r++) oacc[nt][r] = 0.0f;
    float m0 = -1e30f, m1 = -1e30f, l0 = 0.0f, l1 = 0.0f;

    const int nkt = qt + 1;            // 64-wide key tiles (causal)
    const size_t kb = ((size_t)(b * SEQ) * NKV + hk) * HD;
    const size_t vb = ((size_t)(b * NKV + hk) * HD) * SEQ;

    for (int kt = 0; kt < nkt; kt++) {
        const int k0 = kt * 64;

        // ---- load K tile (64x128 bf16 hi+lo): 2048 float4s / 128 thr ----
#pragma unroll
        for (int i = 0; i < 16; i++) {
            int e  = i * 128 + tid;
            int hl = e >> 10;
            int r  = (e >> 4) & 63;
            int c4 = e & 15;
            const bf16* src = hl ? Kl : Kh;
            bf16* dst = smf + (hl ? SK_L : SK_H);
            *(float4*)&dst[r * KSTR + c4 * 8] =
                *(const float4*)&src[kb + (size_t)(k0 + r) * (NKV * HD) + c4 * 8];
        }
        // ---- load Vt tile (128 d x 64 keys hi+lo): 2048 float4s ----
#pragma unroll
        for (int i = 0; i < 16; i++) {
            int e  = i * 128 + tid;
            int hl = e >> 10;
            int d  = (e >> 3) & 127;
            int c4 = e & 7;
            const bf16* src = hl ? Vtl : Vth;
            bf16* dst = smf + (hl ? SV_L : SV_H);
            *(float4*)&dst[d * VSTR + c4 * 8] =
                *(const float4*)&src[vb + (size_t)d * SEQ + k0 + c4 * 8];
        }
        __syncthreads();

        // ---- S = Q K^T (3xBF16) ----
        float sacc[8][4];
#pragma unroll
        for (int j = 0; j < 8; j++)
#pragma unroll
            for (int r = 0; r < 4; r++) sacc[j][r] = 0.0f;

#pragma unroll
        for (int s = 0; s < 8; s++) {
#pragma unroll
            for (int j = 0; j < 8; j++) {
                int key = j * 8 + g;
                u32 bh0 = *(const u32*)&smf[SK_H + key * KSTR + s * 16 + t4 * 2];
                u32 bh1 = *(const u32*)&smf[SK_H + key * KSTR + s * 16 + 8 + t4 * 2];
                u32 bl0 = *(const u32*)&smf[SK_L + key * KSTR + s * 16 + t4 * 2];
                u32 bl1 = *(const u32*)&smf[SK_L + key * KSTR + s * 16 + 8 + t4 * 2];
                mma_bf16(sacc[j], qfh[s], bh0, bh1);
                mma_bf16(sacc[j], qfh[s], bl0, bl1);
                mma_bf16(sacc[j], qfl[s], bh0, bh1);
            }
        }

        // ---- causal mask (diagonal tile only) ----
        if (k0 + 63 > q0) {
#pragma unroll
            for (int j = 0; j < 8; j++) {
                int c0 = k0 + j * 8 + t4 * 2;
                if (c0     > r0) sacc[j][0] = -1e30f;
                if (c0 + 1 > r0) sacc[j][1] = -1e30f;
                if (c0     > r1) sacc[j][2] = -1e30f;
                if (c0 + 1 > r1) sacc[j][3] = -1e30f;
            }
        }

        // ---- online softmax (row stats within quad) ----
        float rm0 = -1e30f, rm1 = -1e30f;
#pragma unroll
        for (int j = 0; j < 8; j++) {
            rm0 = fmaxf(rm0, fmaxf(sacc[j][0], sacc[j][1]));
            rm1 = fmaxf(rm1, fmaxf(sacc[j][2], sacc[j][3]));
        }
        rm0 = fmaxf(rm0, __shfl_xor_sync(0xffffffffu, rm0, 1));
        rm0 = fmaxf(rm0, __shfl_xor_sync(0xffffffffu, rm0, 2));
        rm1 = fmaxf(rm1, __shfl_xor_sync(0xffffffffu, rm1, 1));
        rm1 = fmaxf(rm1, __shfl_xor_sync(0xffffffffu, rm1, 2));
        float mn0 = fmaxf(m0, rm0), mn1 = fmaxf(m1, rm1);
        float a0 = __expf(m0 - mn0), a1 = __expf(m1 - mn1);
        m0 = mn0; m1 = mn1;
        float rs0 = 0.0f, rs1 = 0.0f;
#pragma unroll
        for (int j = 0; j < 8; j++) {
            sacc[j][0] = __expf(sacc[j][0] - m0);
            sacc[j][1] = __expf(sacc[j][1] - m0);
            sacc[j][2] = __expf(sacc[j][2] - m1);
            sacc[j][3] = __expf(sacc[j][3] - m1);
            rs0 += sacc[j][0] + sacc[j][1];
            rs1 += sacc[j][2] + sacc[j][3];
        }
        rs0 += __shfl_xor_sync(0xffffffffu, rs0, 1);
        rs0 += __shfl_xor_sync(0xffffffffu, rs0, 2);
        rs1 += __shfl_xor_sync(0xffffffffu, rs1, 1);
        rs1 += __shfl_xor_sync(0xffffffffu, rs1, 2);
        l0 = l0 * a0 + rs0;
        l1 = l1 * a1 + rs1;
#pragma unroll
        for (int nt = 0; nt < 16; nt++) {
            oacc[nt][0] *= a0; oacc[nt][1] *= a0;
            oacc[nt][2] *= a1; oacc[nt][3] *= a1;
        }

        // ---- P fragments (C-layout -> A-layout, in registers) ----
        u32 pfh[4][4], pfl[4][4];
#pragma unroll
        for (int s = 0; s < 4; s++) {
            int j0 = 2 * s, j1 = 2 * s + 1;
            float h00, h01, h10, h11, h20, h21, h30, h31;
            h00 = __bfloat162float(__float2bfloat16_rn(sacc[j0][0]));
            h01 = __bfloat162float(__float2bfloat16_rn(sacc[j0][1]));
            h10 = __bfloat162float(__float2bfloat16_rn(sacc[j0][2]));
            h11 = __bfloat162float(__float2bfloat16_rn(sacc[j0][3]));
            h20 = __bfloat162float(__float2bfloat16_rn(sacc[j1][0]));
            h21 = __bfloat162float(__float2bfloat16_rn(sacc[j1][1]));
            h30 = __bfloat162float(__float2bfloat16_rn(sacc[j1][2]));
            h31 = __bfloat162float(__float2bfloat16_rn(sacc[j1][3]));
            pfh[s][0] = pack_bf16(h00, h01);
            pfh[s][1] = pack_bf16(h10, h11);
            pfh[s][2] = pack_bf16(h20, h21);
            pfh[s][3] = pack_bf16(h30, h31);
            pfl[s][0] = pack_bf16(sacc[j0][0] - h00, sacc[j0][1] - h01);
            pfl[s][1] = pack_bf16(sacc[j0][2] - h10, sacc[j0][3] - h11);
            pfl[s][2] = pack_bf16(sacc[j1][0] - h20, sacc[j1][1] - h21);
            pfl[s][3] = pack_bf16(sacc[j1][2] - h30, sacc[j1][3] - h31);
        }

        // ---- O += P V (3xBF16) ----
#pragma unroll
        for (int s = 0; s < 4; s++) {
#pragma unroll
            for (int nt = 0; nt < 16; nt++) {
                int d = nt * 8 + g;
                u32 vh0 = *(const u32*)&smf[SV_H + d * VSTR + s * 16 + t4 * 2];
                u32 vh1 = *(const u32*)&smf[SV_H + d * VSTR + s * 16 + 8 + t4 * 2];
                u32 vl0 = *(const u32*)&smf[SV_L + d * VSTR + s * 16 + t4 * 2];
                u32 vl1 = *(const u32*)&smf[SV_L + d * VSTR + s * 16 + 8 + t4 * 2];
                mma_bf16(oacc[nt], pfh[s], vh0, vh1);
                mma_bf16(oacc[nt], pfh[s], vl0, vl1);
                mma_bf16(oacc[nt], pfl[s], vh0, vh1);
            }
        }
        __syncthreads();
    }

    // ---- epilogue: write bf16 hi/lo (feeds Wo GEMM) ----
    float il0 = 1.0f / l0, il1 = 1.0f / l1;
    const size_t ob0 = ((size_t)(b * SEQ + r0) * NH + h) * HD;
    const size_t ob1 = ((size_t)(b * SEQ + r1) * NH + h) * HD;
#pragma unroll
    for (int nt = 0; nt < 16; nt++) {
        int cb = nt * 8 + t4 * 2;
        float o00 = oacc[nt][0] * il0, o01 = oacc[nt][1] * il0;
        float o10 = oacc[nt][2] * il1, o11 = oacc[nt][3] * il1;
        float h00 = __bfloat162float(__float2bfloat16_rn(o00));
        float h01 = __bfloat162float(__float2bfloat16_rn(o01));
        float h10 = __bfloat162float(__float2bfloat16_rn(o10));
        float h11 = __bfloat162float(__float2bfloat16_rn(o11));
        *(u32*)&Oh[ob0 + cb] = pack_bf16(h00, h01);
        *(u32*)&Oh[ob1 + cb] = pack_bf16(h10, h11);
        *(u32*)&Ol[ob0 + cb] = pack_bf16(o00 - h00, o01 - h01);
        *(u32*)&Ol[ob1 + cb] = pack_bf16(o10 - h10, o11 - h11);
    }
}

// ---------------------------------------------------------------------------
// Launch
// ---------------------------------------------------------------------------
extern "C" void kernel_launch(void* const* d_in, const int* in_sizes, int n_in,
                              void* d_out, int out_size)
{
    const float* hs  = (const float*)d_in[0];
    const int*   pos = (const int*)d_in[1];
    const float* Wq  = (const float*)d_in[2];
    const float* Wk  = (const float*)d_in[3];
    const float* Wv  = (const float*)d_in[4];
    const float* Wo  = (const float*)d_in[5];
    float*       out = (float*)d_out;

    float *qkv;
    bf16 *wtbh, *wtbl, *hsh, *hsl, *attnh, *attnl;
    bf16 *qh, *ql, *kh, *kl, *vth, *vtl;
    cudaGetSymbolAddress((void**)&qkv,   g_qkv);
    cudaGetSymbolAddress((void**)&wtbh,  g_wtbh);
    cudaGetSymbolAddress((void**)&wtbl,  g_wtbl);
    cudaGetSymbolAddress((void**)&hsh,   g_hsh);
    cudaGetSymbolAddress((void**)&hsl,   g_hsl);
    cudaGetSymbolAddress((void**)&attnh, g_attnh);
    cudaGetSymbolAddress((void**)&attnl, g_attnl);
    cudaGetSymbolAddress((void**)&qh,    g_qh);
    cudaGetSymbolAddress((void**)&ql,    g_ql);
    cudaGetSymbolAddress((void**)&kh,    g_kh);
    cudaGetSymbolAddress((void**)&kl,    g_kl);
    cudaGetSymbolAddress((void**)&vth,   g_vth);
    cudaGetSymbolAddress((void**)&vtl,   g_vtl);

    cudaFuncSetAttribute(flash_mma_kernel,
                         cudaFuncAttributeMaxDynamicSharedMemorySize, FLASH_SMEM);
    cudaFuncSetAttribute(gemm_bf16_kernel,
                         cudaFuncAttributeMaxDynamicSharedMemorySize, GEMM_SMEM);

    // Weight transpose + bf16 split: QKV packed [3072][2048], Wo after
    transpose_split_kernel<<<dim3(2048/32, 2048/32), dim3(32, 8)>>>(
        Wq, wtbh + WT_OFF_QKV,                  wtbl + WT_OFF_QKV,                  HSZ, 2048);
    transpose_split_kernel<<<dim3(512/32, 2048/32), dim3(32, 8)>>>(
        Wk, wtbh + WT_OFF_QKV + 2048*HSZ,       wtbl + WT_OFF_QKV + 2048*HSZ,       HSZ, 512);
    transpose_split_kernel<<<dim3(512/32, 2048/32), dim3(32, 8)>>>(
        Wv, wtbh + WT_OFF_QKV + 2560*HSZ,       wtbl + WT_OFF_QKV + 2560*HSZ,       HSZ, 512);
    transpose_split_kernel<<<dim3(2048/32, 2048/32), dim3(32, 8)>>>(
        Wo, wtbh + WT_OFF_O,                    wtbl + WT_OFF_O,                    HSZ, 2048);

    // hidden_states bf16 split
    split_act_kernel<<<(NTOK * HSZ / 4 + 255) / 256, 256>>>(
        hs, hsh, hsl, NTOK * HSZ / 4);

    // Fused QKV projection (3xBF16 cp.async GEMM, N=3072)
    gemm_bf16_kernel<<<dim3(3072/128, NTOK/256), 512, GEMM_SMEM>>>(
        hsh, hsl, wtbh + WT_OFF_QKV, wtbl + WT_OFF_QKV, qkv, 3072);

    // RoPE + bf16 split; V transpose+split (all read from strided qkv)
    {
        int total_q = NTOK * NH * 64;
        int total_k = NTOK * NKV * 64;
        rope_split_kernel<<<(total_q + 255) / 256, 256>>>(
            qkv, 3072, qh, ql, pos, NH, total_q, 0.08838834764831845f);
        rope_split_kernel<<<(total_k + 255) / 256, 256>>>(
            qkv + 2048, 3072, kh, kl, pos, NKV, total_k, 1.0f);
        vt_split_kernel<<<dim3(SEQ/32, HD/32, BATCH*NKV), dim3(32, 8)>>>(
            qkv + 2560, 3072, vth, vtl);
    }

    // Causal GQA attention (3xBF16, 64-query CTAs, 2 CTAs/SM)
    flash_mma_kernel<<<dim3(SEQ/64, NH, BATCH), 128, FLASH_SMEM>>>(
        qh, ql, kh, kl, vth, vtl, attnh, attnl);

    // Output projection (3xBF16 cp.async GEMM)
    gemm_bf16_kernel<<<dim3(2048/128, NTOK/256), 512, GEMM_SMEM>>>(
        attnh, attnl, wtbh + WT_OFF_O, wtbl + WT_OFF_O, out, 2048);
}